// round 5
// baseline (speedup 1.0000x reference)
#include <cuda_runtime.h>
#include <cuda_fp16.h>
#include <cooperative_groups.h>
namespace cg = cooperative_groups;

// ---------------- static scratch (no allocation allowed) ----------------
#define N_MAX 100032
#define E_MAX 3400000
#define BLK 256

__device__ __align__(256) __half d_h1h[100000 * 64]; // h1 * dinv, fp16
__device__ __align__(256) float d_z[100000 * 2];     // (relu(g1)@W2f) * dinv
__device__ __align__(256) float d_logits[100000 * 2];
__device__ __align__(256) int   d_cnt[N_MAX];        // in-degree histogram (excl self)
__device__ __align__(256) int   d_roff[N_MAX + 1];   // CSR row offsets
__device__ __align__(256) int   d_cursor[N_MAX];     // scatter cursors
__device__ __align__(256) int   d_ssrc[E_MAX];       // src sorted by dst
__device__ __align__(256) int   d_blk[256];          // scan block sums
__device__ float d_W2f[64 * 2];                      // W2 @ Wl1 @ Wl2
__device__ float d_bc[2];                            // folded bias
__device__ float d_csum[2];

// ---------------- helpers ----------------
__device__ __forceinline__ void fma2(unsigned long long& d, unsigned long long a, unsigned long long b) {
    asm("fma.rn.f32x2 %0, %1, %2, %0;" : "+l"(d) : "l"(a), "l"(b));
}
__device__ __forceinline__ unsigned long long pk2(float lo, float hi) {
    unsigned long long r;
    asm("mov.b64 %0, {%1, %2};" : "=l"(r) : "f"(lo), "f"(hi));
    return r;
}
__device__ __forceinline__ float2 upk2(unsigned long long v) {
    float2 f;
    asm("mov.b64 {%0, %1}, %2;" : "=f"(f.x), "=f"(f.y) : "l"(v));
    return f;
}

struct SmemU {
    union {
        struct { float xs[64][33]; float ws[32][64]; } g;   // gemm tiles
        struct { int s[BLK]; } scan;
        struct { float A[64][2]; } fold;
        float wf[128];
        float red[64];
    };
};

__global__ void __launch_bounds__(BLK, 4)
k_mega(const float* __restrict__ x, const int* __restrict__ src, const int* __restrict__ dst,
       const float* __restrict__ W1, const float* __restrict__ b1,
       const float* __restrict__ W2, const float* __restrict__ b2,
       const float* __restrict__ Wl1, const float* __restrict__ bl1,
       const float* __restrict__ Wl2, const float* __restrict__ bl2,
       float* __restrict__ out, int n, int E)
{
    __shared__ SmemU sm;
    cg::grid_group grid = cg::this_grid();

    const int t = threadIdx.x;
    const int bid = blockIdx.x;
    const int nblk = gridDim.x;
    const int gtid = bid * BLK + t;
    const int gthreads = nblk * BLK;
    const int lane = t & 31;
    const int wid = t >> 5;
    const int gwid = gtid >> 5;
    const int nwarps = gthreads >> 5;

    // ---------------- P0: zero cnt, reset csum, fold small weights ----------------
    for (int i = gtid; i < n; i += gthreads) d_cnt[i] = 0;
    if (gtid == 0) { d_csum[0] = 0.f; d_csum[1] = 0.f; }
    if (bid == 0) {
        if (t < 64) {
            float a0 = 0.f, a1 = 0.f;
            for (int m = 0; m < 32; m++) {
                float w = Wl1[t * 32 + m];
                a0 += w * Wl2[m * 2 + 0];
                a1 += w * Wl2[m * 2 + 1];
            }
            sm.fold.A[t][0] = a0; sm.fold.A[t][1] = a1;
        }
        __syncthreads();
        if (t < 64) {
            float f0 = 0.f, f1 = 0.f;
            for (int j = 0; j < 64; j++) {
                float w = W2[t * 64 + j];
                f0 += w * sm.fold.A[j][0];
                f1 += w * sm.fold.A[j][1];
            }
            d_W2f[t * 2 + 0] = f0;
            d_W2f[t * 2 + 1] = f1;
        }
        if (t < 2) {
            float b = bl2[t];
            for (int j = 0; j < 64; j++) b += b2[j] * sm.fold.A[j][t];
            for (int m = 0; m < 32; m++) b += bl1[m] * Wl2[m * 2 + t];
            d_bc[t] = b;
        }
        __syncthreads();
    }
    grid.sync();

    // ---------------- P1: degree histogram ----------------
    for (int e = gtid; e < E; e += gthreads) atomicAdd(&d_cnt[dst[e]], 1);
    grid.sync();

    // ---------------- P2: gemm1  h1p = (x@W1)*dinv -> fp16 ----------------
    {
        int ty = t >> 4, tx = t & 15;
        int ntiles = (n + 63) / 64;
        for (int tile = bid; tile < ntiles; tile += nblk) {
            int m0 = tile * 64;
            unsigned long long acc[4][2] = {};
            for (int kc = 0; kc < 128; kc += 32) {
                #pragma unroll
                for (int q = 0; q < 2; q++) {             // x tile 64x32
                    int id = t + q * 256;
                    int r = id >> 3;
                    int c = (id & 7) * 4;
                    int node = m0 + r;
                    float4 v = make_float4(0.f, 0.f, 0.f, 0.f);
                    if (node < n) v = *(const float4*)&x[node * 128 + kc + c];
                    sm.g.xs[r][c + 0] = v.x; sm.g.xs[r][c + 1] = v.y;
                    sm.g.xs[r][c + 2] = v.z; sm.g.xs[r][c + 3] = v.w;
                }
                #pragma unroll
                for (int q = 0; q < 2; q++) {             // W tile 32x64
                    int id = t + q * 256;
                    int r = id >> 4;
                    int c = (id & 15) * 4;
                    *(float4*)&sm.g.ws[r][c] = *(const float4*)&W1[(kc + r) * 64 + c];
                }
                __syncthreads();
                #pragma unroll
                for (int k = 0; k < 32; k++) {
                    float4 b = *(float4*)&sm.g.ws[k][tx * 4];
                    unsigned long long b01 = pk2(b.x, b.y);
                    unsigned long long b23 = pk2(b.z, b.w);
                    #pragma unroll
                    for (int i2 = 0; i2 < 4; i2++) {
                        float a = sm.g.xs[ty * 4 + i2][k];
                        unsigned long long aa = pk2(a, a);
                        fma2(acc[i2][0], aa, b01);
                        fma2(acc[i2][1], aa, b23);
                    }
                }
                __syncthreads();
            }
            #pragma unroll
            for (int i2 = 0; i2 < 4; i2++) {
                int node = m0 + ty * 4 + i2;
                if (node < n) {
                    float s = rsqrtf((float)d_cnt[node] + 1.0f);
                    float2 p0 = upk2(acc[i2][0]);
                    float2 p1 = upk2(acc[i2][1]);
                    __half2 h0 = __floats2half2_rn(p0.x * s, p0.y * s);
                    __half2 h1 = __floats2half2_rn(p1.x * s, p1.y * s);
                    __half2* op = (__half2*)&d_h1h[node * 64 + tx * 4];
                    op[0] = h0; op[1] = h1;
                }
            }
        }
    }
    grid.sync();

    // ---------------- P3: scan (CSR offsets), fixed 1024-node chunks ----------------
    const int CH = 1024;
    int nscan = (n + CH - 1) / CH;    // <= 256 for n <= 262144
    if (bid < nscan) {                 // P3a: block sums
        int base = bid * CH + t * 4;
        int s = 0;
        #pragma unroll
        for (int j = 0; j < 4; j++) { int i = base + j; if (i < n) s += d_cnt[i]; }
        sm.scan.s[t] = s; __syncthreads();
        for (int o = 1; o < 256; o <<= 1) {
            int tv = (t >= o) ? sm.scan.s[t - o] : 0;
            __syncthreads();
            sm.scan.s[t] += tv;
            __syncthreads();
        }
        if (t == 255) d_blk[bid] = sm.scan.s[255];
    }
    grid.sync();
    if (bid == 0) {                    // P3b: exclusive scan of block sums
        int v = (t < nscan) ? d_blk[t] : 0;
        sm.scan.s[t] = v; __syncthreads();
        for (int o = 1; o < 256; o <<= 1) {
            int tv = (t >= o) ? sm.scan.s[t - o] : 0;
            __syncthreads();
            sm.scan.s[t] += tv;
            __syncthreads();
        }
        if (t < nscan) d_blk[t] = sm.scan.s[t] - v;
    }
    grid.sync();
    if (bid < nscan) {                 // P3c: final offsets + cursors
        int base = bid * CH + t * 4;
        int v[4];
        #pragma unroll
        for (int j = 0; j < 4; j++) { int i = base + j; v[j] = (i < n) ? d_cnt[i] : 0; }
        int tsum = v[0] + v[1] + v[2] + v[3];
        sm.scan.s[t] = tsum; __syncthreads();
        for (int o = 1; o < 256; o <<= 1) {
            int tv = (t >= o) ? sm.scan.s[t - o] : 0;
            __syncthreads();
            sm.scan.s[t] += tv;
            __syncthreads();
        }
        int run = sm.scan.s[t] - tsum + d_blk[bid];
        #pragma unroll
        for (int j = 0; j < 4; j++) {
            int i = base + j;
            if (i < n) { d_roff[i] = run; d_cursor[i] = run; }
            run += v[j];
        }
    }
    if (gtid == 0) d_roff[n] = E;
    grid.sync();

    // ---------------- P4: scatter (sort src by dst) ----------------
    for (int e = gtid; e < E; e += gthreads) {
        int p = atomicAdd(&d_cursor[dst[e]], 1);
        d_ssrc[p] = src[e];
    }
    grid.sync();

    // ---------------- P5: fused agg1 + relu + projection -> z ----------------
    if (t < 128) sm.wf[t] = d_W2f[t];
    __syncthreads();
    {
        const __half2* hp = (const __half2*)d_h1h;
        int c = lane * 2;
        float2 bv = *(const float2*)&b1[c];
        float w00 = sm.wf[2 * c + 0], w01 = sm.wf[2 * c + 1];
        float w10 = sm.wf[2 * c + 2], w11 = sm.wf[2 * c + 3];
        for (int w = gwid; w < n; w += nwarps) {
            int start = d_roff[w];
            int cnt   = d_roff[w + 1] - start;
            float ax = 0.f, ay = 0.f;
            const int* sp = &d_ssrc[start];
            int j = 0;
            for (; j + 4 <= cnt; j += 4) {
                int s0 = __ldg(&sp[j + 0]);
                int s1 = __ldg(&sp[j + 1]);
                int s2 = __ldg(&sp[j + 2]);
                int s3 = __ldg(&sp[j + 3]);
                float2 a0 = __half22float2(hp[s0 * 32 + lane]);
                float2 a1 = __half22float2(hp[s1 * 32 + lane]);
                float2 a2 = __half22float2(hp[s2 * 32 + lane]);
                float2 a3 = __half22float2(hp[s3 * 32 + lane]);
                ax += (a0.x + a1.x) + (a2.x + a3.x);
                ay += (a0.y + a1.y) + (a2.y + a3.y);
            }
            for (; j < cnt; j++) {
                int s0 = __ldg(&sp[j]);
                float2 a0 = __half22float2(hp[s0 * 32 + lane]);
                ax += a0.x; ay += a0.y;
            }
            float s = rsqrtf((float)cnt + 1.0f);
            float2 self = __half22float2(hp[w * 32 + lane]);
            float gx = fmaxf(s * (ax + self.x) + bv.x, 0.f);
            float gy = fmaxf(s * (ay + self.y) + bv.y, 0.f);
            float z0 = gx * w00 + gy * w10;
            float z1 = gx * w01 + gy * w11;
            #pragma unroll
            for (int o = 16; o; o >>= 1) {
                z0 += __shfl_xor_sync(0xffffffffu, z0, o);
                z1 += __shfl_xor_sync(0xffffffffu, z1, o);
            }
            if (lane == 0)
                ((float2*)d_z)[w] = make_float2(z0 * s, z1 * s);
        }
    }
    grid.sync();

    // ---------------- P6: fused agg2 -> logits, accumulate exp sums ----------------
    {
        float bc0 = d_bc[0], bc1 = d_bc[1];
        float ps0 = 0.f, ps1 = 0.f;
        for (int w = gwid; w < n; w += nwarps) {
            int start = d_roff[w];
            int end   = d_roff[w + 1];
            float z0 = 0.f, z1 = 0.f;
            for (int j = start + lane; j < end; j += 32) {
                int si = __ldg(&d_ssrc[j]);
                float2 zz = ((const float2*)d_z)[si];
                z0 += zz.x; z1 += zz.y;
            }
            #pragma unroll
            for (int o = 16; o; o >>= 1) {
                z0 += __shfl_xor_sync(0xffffffffu, z0, o);
                z1 += __shfl_xor_sync(0xffffffffu, z1, o);
            }
            if (lane == 0) {
                float s = rsqrtf((float)(end - start) + 1.0f);
                float2 self = ((const float2*)d_z)[w];
                float l0 = s * (z0 + self.x) + bc0;
                float l1 = s * (z1 + self.y) + bc1;
                ((float2*)d_logits)[w] = make_float2(l0, l1);
                ps0 += expf(l0);
                ps1 += expf(l1);
            }
        }
        // block reduce (only lane0 values nonzero)
        #pragma unroll
        for (int o = 16; o; o >>= 1) {
            ps0 += __shfl_xor_sync(0xffffffffu, ps0, o);
            ps1 += __shfl_xor_sync(0xffffffffu, ps1, o);
        }
        if (lane == 0) { sm.red[2 * wid] = ps0; sm.red[2 * wid + 1] = ps1; }
        __syncthreads();
        if (t == 0) {
            float s0 = 0.f, s1 = 0.f;
            for (int q = 0; q < 8; q++) { s0 += sm.red[2 * q]; s1 += sm.red[2 * q + 1]; }
            atomicAdd(&d_csum[0], s0);
            atomicAdd(&d_csum[1], s1);
        }
    }
    grid.sync();

    // ---------------- P7: normalize ----------------
    {
        float r0 = 1.0f / d_csum[0], r1 = 1.0f / d_csum[1];
        for (int i = gtid; i < n; i += gthreads) {
            float2 l = ((const float2*)d_logits)[i];
            out[2 * i + 0] = expf(l.x) * r0;
            out[2 * i + 1] = expf(l.y) * r1;
        }
    }
}

// ---------------- launch ----------------
extern "C" void kernel_launch(void* const* d_in, const int* in_sizes, int n_in,
                              void* d_out, int out_size) {
    const float* x   = (const float*)d_in[0];
    const int*   ei  = (const int*)d_in[1];     // int32 (JAX x64 disabled)
    const float* W1  = (const float*)d_in[2];
    const float* b1  = (const float*)d_in[3];
    const float* W2  = (const float*)d_in[4];
    const float* b2  = (const float*)d_in[5];
    const float* Wl1 = (const float*)d_in[6];
    const float* bl1 = (const float*)d_in[7];
    const float* Wl2 = (const float*)d_in[8];
    const float* bl2 = (const float*)d_in[9];
    float* out = (float*)d_out;

    int n = in_sizes[0] / 128;
    int E = in_sizes[1] / 2;
    const int* src = ei;
    const int* dst = ei + E;

    static int grid = 0;
    if (!grid) {
        int dev = 0;
        cudaGetDevice(&dev);
        int sms = 0;
        cudaDeviceGetAttribute(&sms, cudaDevAttrMultiProcessorCount, dev);
        int bpm = 0;
        cudaOccupancyMaxActiveBlocksPerMultiprocessor(&bpm, k_mega, BLK, 0);
        if (bpm < 1) bpm = 1;
        grid = sms * bpm;
        if (grid > 2048) grid = 2048;
        if (grid < 128) grid = 128;
    }

    void* args[] = { (void*)&x, (void*)&src, (void*)&dst,
                     (void*)&W1, (void*)&b1, (void*)&W2, (void*)&b2,
                     (void*)&Wl1, (void*)&bl1, (void*)&Wl2, (void*)&bl2,
                     (void*)&out, (void*)&n, (void*)&E };
    cudaLaunchCooperativeKernel((const void*)k_mega, dim3(grid), dim3(BLK), args, 0, 0);
}

// round 6
// speedup vs baseline: 1.1713x; 1.1713x over previous
#include <cuda_runtime.h>
#include <cuda_fp16.h>

// ---------------- static scratch (no allocation allowed) ----------------
#define N_MAX 100032
#define E_MAX 3400000

__device__ __align__(256) __half d_h1h[100000 * 64]; // h1 (UNSCALED), fp16
__device__ __align__(256) float d_dinv[N_MAX];
__device__ __align__(256) float d_z[100000 * 2];     // (relu(g1)@W2f) * dinv
__device__ __align__(256) float d_logits[100000 * 2];
__device__ __align__(256) int   d_cnt[N_MAX];        // in-degree histogram (excl self)
__device__ __align__(256) int   d_roff[N_MAX + 1];   // CSR row offsets
__device__ __align__(256) int   d_cursor[N_MAX];     // scatter cursors
__device__ __align__(256) int   d_ssrc[E_MAX];       // src sorted by dst
__device__ __align__(256) int   d_blk[256];          // scan block sums
__device__ float d_W2f[64 * 2];                      // W2 @ Wl1 @ Wl2
__device__ float d_bc[2];                            // folded bias
__device__ float d_csum[2];

// ---------------- helpers ----------------
__device__ __forceinline__ void fma2(unsigned long long& d, unsigned long long a, unsigned long long b) {
    asm("fma.rn.f32x2 %0, %1, %2, %0;" : "+l"(d) : "l"(a), "l"(b));
}
__device__ __forceinline__ unsigned long long pk2(float lo, float hi) {
    unsigned long long r;
    asm("mov.b64 %0, {%1, %2};" : "=l"(r) : "f"(lo), "f"(hi));
    return r;
}
__device__ __forceinline__ float2 upk2(unsigned long long v) {
    float2 f;
    asm("mov.b64 {%0, %1}, %2;" : "=f"(f.x), "=f"(f.y) : "l"(v));
    return f;
}

// ---------------- CSR build ----------------
__global__ void k_init0(int n) {
    int i = blockIdx.x * blockDim.x + threadIdx.x;
    if (i < n) d_cnt[i] = 0;
    if (i < 2) d_csum[i] = 0.0f;
}

__global__ void k_hist(const int* __restrict__ dst, int E) {
    int e = blockIdx.x * blockDim.x + threadIdx.x;
    if (e < E) atomicAdd(&d_cnt[dst[e]], 1);
}

__global__ void k_scanA(int n) {
    __shared__ int sh[256];
    int t = threadIdx.x, b = blockIdx.x;
    int base = b * 1024 + t * 4;
    int s = 0;
    #pragma unroll
    for (int j = 0; j < 4; j++) { int i = base + j; if (i < n) s += d_cnt[i]; }
    sh[t] = s; __syncthreads();
    #pragma unroll
    for (int o = 128; o; o >>= 1) {
        if (t < o) sh[t] += sh[t + o];
        __syncthreads();
    }
    if (t == 0) d_blk[b] = sh[0];
}

__global__ void k_scanB(int nb) {
    __shared__ int sh[256];
    int t = threadIdx.x;
    int v = (t < nb) ? d_blk[t] : 0;
    sh[t] = v; __syncthreads();
    for (int o = 1; o < 256; o <<= 1) {
        int tv = (t >= o) ? sh[t - o] : 0;
        __syncthreads();
        sh[t] += tv;
        __syncthreads();
    }
    if (t < nb) d_blk[t] = sh[t] - v;   // exclusive
}

// scanC: final offsets + cursors + dinv
__global__ void k_scanC(int n) {
    __shared__ int sh[256];
    int t = threadIdx.x, b = blockIdx.x;
    int base = b * 1024 + t * 4;
    int v[4];
    #pragma unroll
    for (int j = 0; j < 4; j++) { int i = base + j; v[j] = (i < n) ? d_cnt[i] : 0; }
    int tsum = v[0] + v[1] + v[2] + v[3];
    sh[t] = tsum; __syncthreads();
    for (int o = 1; o < 256; o <<= 1) {
        int tv = (t >= o) ? sh[t - o] : 0;
        __syncthreads();
        sh[t] += tv;
        __syncthreads();
    }
    int run = sh[t] - tsum + d_blk[b];
    #pragma unroll
    for (int j = 0; j < 4; j++) {
        int i = base + j;
        if (i < n) {
            d_roff[i] = run;
            d_cursor[i] = run;
            d_dinv[i] = rsqrtf((float)v[j] + 1.0f);
        }
        run += v[j];
        if (i == n - 1) d_roff[n] = run;
    }
}

__global__ void k_scatter(const int* __restrict__ src, const int* __restrict__ dst, int E) {
    int e = blockIdx.x * blockDim.x + threadIdx.x;
    if (e >= E) return;
    int p = atomicAdd(&d_cursor[dst[e]], 1);
    d_ssrc[p] = src[e];
}

// ---------------- dense math ----------------

// h1 = x @ W1 -> fp16 (UNSCALED; dinv applied at aggregation time).
// Independent of the CSR build -> runs concurrently on stream s1.
__global__ void k_gemm1(const float* __restrict__ x, const float* __restrict__ W, int n) {
    __shared__ float xs[64][33];
    __shared__ float ws[32][64];
    int t  = threadIdx.x;
    int ty = t >> 4, tx = t & 15;
    int m0 = blockIdx.x * 64;
    unsigned long long acc[4][2] = {};

    for (int kc = 0; kc < 128; kc += 32) {
        #pragma unroll
        for (int q = 0; q < 2; q++) {                 // x tile: 64x32
            int id = t + q * 256;
            int r = id >> 3;
            int c = (id & 7) * 4;
            int node = m0 + r;
            float4 v = make_float4(0.f, 0.f, 0.f, 0.f);
            if (node < n) v = *(const float4*)&x[node * 128 + kc + c];
            xs[r][c + 0] = v.x; xs[r][c + 1] = v.y;
            xs[r][c + 2] = v.z; xs[r][c + 3] = v.w;
        }
        #pragma unroll
        for (int q = 0; q < 2; q++) {                 // W tile: 32x64
            int id = t + q * 256;
            int r = id >> 4;
            int c = (id & 15) * 4;
            *(float4*)&ws[r][c] = *(const float4*)&W[(kc + r) * 64 + c];
        }
        __syncthreads();
        #pragma unroll
        for (int k = 0; k < 32; k++) {
            float4 b = *(float4*)&ws[k][tx * 4];
            unsigned long long b01 = pk2(b.x, b.y);
            unsigned long long b23 = pk2(b.z, b.w);
            #pragma unroll
            for (int i2 = 0; i2 < 4; i2++) {
                float a = xs[ty * 4 + i2][k];
                unsigned long long aa = pk2(a, a);
                fma2(acc[i2][0], aa, b01);
                fma2(acc[i2][1], aa, b23);
            }
        }
        __syncthreads();
    }
    #pragma unroll
    for (int i2 = 0; i2 < 4; i2++) {
        int node = m0 + ty * 4 + i2;
        if (node < n) {
            float2 p0 = upk2(acc[i2][0]);
            float2 p1 = upk2(acc[i2][1]);
            __half2* op = (__half2*)&d_h1h[node * 64 + tx * 4];
            op[0] = __floats2half2_rn(p0.x, p0.y);
            op[1] = __floats2half2_rn(p1.x, p1.y);
        }
    }
}

// fold W2 @ Wl1 @ Wl2 -> d_W2f[64][2]; folded bias -> d_bc
__global__ void k_fold(const float* __restrict__ W2, const float* __restrict__ Wl1,
                       const float* __restrict__ Wl2, const float* __restrict__ b2,
                       const float* __restrict__ bl1, const float* __restrict__ bl2) {
    __shared__ float A[64][2];
    int i = threadIdx.x;            // 64 threads
    float a0 = 0.f, a1 = 0.f;
    for (int m = 0; m < 32; m++) {
        float w = Wl1[i * 32 + m];
        a0 += w * Wl2[m * 2 + 0];
        a1 += w * Wl2[m * 2 + 1];
    }
    A[i][0] = a0; A[i][1] = a1;
    __syncthreads();
    float f0 = 0.f, f1 = 0.f;
    for (int j = 0; j < 64; j++) {
        float w = W2[i * 64 + j];
        f0 += w * A[j][0];
        f1 += w * A[j][1];
    }
    d_W2f[i * 2 + 0] = f0;
    d_W2f[i * 2 + 1] = f1;
    if (i < 2) {
        float b = bl2[i];
        for (int j = 0; j < 64; j++) b += b2[j] * A[j][i];
        for (int m = 0; m < 32; m++) b += bl1[m] * Wl2[m * 2 + i];
        d_bc[i] = b;
    }
}

// ---------------- fused pull-aggregation #1 ----------------
// warp per node: acc += dinv[src] * h1[src]; then dinv*(acc+dinv[w]*h1[w])+b1,
// relu, project to 2 via W2f, *dinv -> d_z.
__global__ void k_agg1z(const float* __restrict__ b1, int n) {
    __shared__ float wf[128];
    if (threadIdx.x < 128) wf[threadIdx.x] = d_W2f[threadIdx.x];
    __syncthreads();

    int w = (blockIdx.x * blockDim.x + threadIdx.x) >> 5;
    if (w >= n) return;
    int lane = threadIdx.x & 31;
    int c = lane * 2;

    int start = d_roff[w];
    int cnt   = d_roff[w + 1] - start;

    const __half2* hp = (const __half2*)d_h1h;
    float ax = 0.f, ay = 0.f;
    const int* sp = &d_ssrc[start];
    int j = 0;
    for (; j + 4 <= cnt; j += 4) {
        int s0 = __ldg(&sp[j + 0]);
        int s1 = __ldg(&sp[j + 1]);
        int s2 = __ldg(&sp[j + 2]);
        int s3 = __ldg(&sp[j + 3]);
        float d0 = __ldg(&d_dinv[s0]);
        float d1 = __ldg(&d_dinv[s1]);
        float d2 = __ldg(&d_dinv[s2]);
        float d3 = __ldg(&d_dinv[s3]);
        float2 a0 = __half22float2(hp[s0 * 32 + lane]);
        float2 a1 = __half22float2(hp[s1 * 32 + lane]);
        float2 a2 = __half22float2(hp[s2 * 32 + lane]);
        float2 a3 = __half22float2(hp[s3 * 32 + lane]);
        ax += a0.x * d0 + a1.x * d1 + a2.x * d2 + a3.x * d3;
        ay += a0.y * d0 + a1.y * d1 + a2.y * d2 + a3.y * d3;
    }
    for (; j < cnt; j++) {
        int s0 = __ldg(&sp[j]);
        float d0 = __ldg(&d_dinv[s0]);
        float2 a0 = __half22float2(hp[s0 * 32 + lane]);
        ax += a0.x * d0; ay += a0.y * d0;
    }

    float s = d_dinv[w];
    float2 self = __half22float2(hp[w * 32 + lane]);
    float2 bv   = *(const float2*)&b1[c];
    float gx = fmaxf(s * (ax + self.x * s) + bv.x, 0.f);
    float gy = fmaxf(s * (ay + self.y * s) + bv.y, 0.f);

    float z0 = gx * wf[2 * c + 0] + gy * wf[2 * c + 2];
    float z1 = gx * wf[2 * c + 1] + gy * wf[2 * c + 3];
    #pragma unroll
    for (int o = 16; o; o >>= 1) {
        z0 += __shfl_xor_sync(0xffffffffu, z0, o);
        z1 += __shfl_xor_sync(0xffffffffu, z1, o);
    }
    if (lane == 0)
        ((float2*)d_z)[w] = make_float2(z0 * s, z1 * s);
}

// ---------------- fused pull-aggregation #2 + logits + exp-sum ----------------
__global__ void k_agg2l(int n) {
    __shared__ float red[16];
    int w = (blockIdx.x * blockDim.x + threadIdx.x) >> 5;
    int lane = threadIdx.x & 31;
    int wid = threadIdx.x >> 5;

    float e0 = 0.f, e1 = 0.f;
    if (w < n) {
        int start = d_roff[w];
        int end   = d_roff[w + 1];
        float z0 = 0.f, z1 = 0.f;
        for (int j = start + lane; j < end; j += 32) {
            int si = __ldg(&d_ssrc[j]);
            float2 zz = ((const float2*)d_z)[si];
            z0 += zz.x; z1 += zz.y;
        }
        #pragma unroll
        for (int o = 16; o; o >>= 1) {
            z0 += __shfl_xor_sync(0xffffffffu, z0, o);
            z1 += __shfl_xor_sync(0xffffffffu, z1, o);
        }
        if (lane == 0) {
            float s = d_dinv[w];
            float2 self = ((const float2*)d_z)[w];
            float l0 = s * (z0 + self.x) + d_bc[0];
            float l1 = s * (z1 + self.y) + d_bc[1];
            ((float2*)d_logits)[w] = make_float2(l0, l1);
            e0 = expf(l0);
            e1 = expf(l1);
        }
    }
    // block-level exp-sum reduce (lane0 values only)
    #pragma unroll
    for (int o = 16; o; o >>= 1) {
        e0 += __shfl_xor_sync(0xffffffffu, e0, o);
        e1 += __shfl_xor_sync(0xffffffffu, e1, o);
    }
    if (lane == 0) { red[2 * wid] = e0; red[2 * wid + 1] = e1; }
    __syncthreads();
    if (threadIdx.x == 0) {
        float s0 = 0.f, s1 = 0.f;
        for (int q = 0; q < 8; q++) { s0 += red[2 * q]; s1 += red[2 * q + 1]; }
        atomicAdd(&d_csum[0], s0);
        atomicAdd(&d_csum[1], s1);
    }
}

__global__ void k_out(float* __restrict__ out, int n) {
    int i = blockIdx.x * blockDim.x + threadIdx.x;
    if (i >= n) return;
    float r0 = 1.0f / d_csum[0], r1 = 1.0f / d_csum[1];
    float2 l = ((const float2*)d_logits)[i];
    out[2 * i + 0] = expf(l.x) * r0;
    out[2 * i + 1] = expf(l.y) * r1;
}

// ---------------- launch ----------------
extern "C" void kernel_launch(void* const* d_in, const int* in_sizes, int n_in,
                              void* d_out, int out_size) {
    const float* x   = (const float*)d_in[0];
    const int*   ei  = (const int*)d_in[1];     // int32 (JAX x64 disabled)
    const float* W1  = (const float*)d_in[2];
    const float* b1  = (const float*)d_in[3];
    const float* W2  = (const float*)d_in[4];
    const float* b2  = (const float*)d_in[5];
    const float* Wl1 = (const float*)d_in[6];
    const float* bl1 = (const float*)d_in[7];
    const float* Wl2 = (const float*)d_in[8];
    const float* bl2 = (const float*)d_in[9];
    float* out = (float*)d_out;

    int n = in_sizes[0] / 128;
    int E = in_sizes[1] / 2;
    const int* src = ei;
    const int* dst = ei + E;
    int nb = (n + 1023) / 1024;

    static cudaStream_t s1 = 0;
    static cudaEvent_t evFork = 0, evGemm = 0;
    if (!s1) {
        cudaStreamCreateWithFlags(&s1, cudaStreamNonBlocking);
        cudaEventCreateWithFlags(&evFork, cudaEventDisableTiming);
        cudaEventCreateWithFlags(&evGemm, cudaEventDisableTiming);
    }

    // fork: gemm1 (independent of CSR build) on s1
    cudaEventRecord(evFork, 0);
    cudaStreamWaitEvent(s1, evFork, 0);
    k_gemm1 <<<(n + 63) / 64, 256, 0, s1>>>(x, W1, n);
    k_fold  <<<1, 64, 0, s1>>>(W2, Wl1, Wl2, b2, bl1, bl2);
    cudaEventRecord(evGemm, s1);

    // CSR build chain on stream 0
    k_init0  <<<(n + 255) / 256, 256>>>(n);
    k_hist   <<<(E + 255) / 256, 256>>>(dst, E);
    k_scanA  <<<nb, 256>>>(n);
    k_scanB  <<<1, 256>>>(nb);
    k_scanC  <<<nb, 256>>>(n);
    k_scatter<<<(E + 255) / 256, 256>>>(src, dst, E);

    // join: aggregation needs both
    cudaStreamWaitEvent(0, evGemm, 0);
    k_agg1z  <<<(n * 32 + 255) / 256, 256>>>(b1, n);
    k_agg2l  <<<(n * 32 + 255) / 256, 256>>>(n);
    k_out    <<<(n + 255) / 256, 256>>>(out, n);
}

// round 7
// speedup vs baseline: 1.2352x; 1.0545x over previous
#include <cuda_runtime.h>
#include <cuda_fp16.h>

// ---------------- static scratch (no allocation allowed) ----------------
#define N_MAX 100032
#define E_MAX 3400000

__device__ __align__(256) __half d_h1h[100000 * 64]; // h1 * dinv (prescaled), fp16
__device__ __align__(256) float d_z[100000 * 2];     // (relu(g1)@W2f) * dinv
__device__ __align__(256) float d_logits[100000 * 2];
__device__ __align__(256) int   d_cnt[N_MAX];        // in-degree histogram (excl self)
__device__ __align__(256) int   d_roff[N_MAX + 1];   // CSR row offsets
__device__ __align__(256) int   d_cursor[N_MAX];     // scatter cursors
__device__ __align__(256) int   d_ssrc[E_MAX];       // src sorted by dst
__device__ __align__(256) int   d_blk[256];          // scan block sums
__device__ float d_W2f[64 * 2];                      // W2 @ Wl1 @ Wl2
__device__ float d_bc[2];                            // folded bias
__device__ float d_csum[2];

// ---------------- helpers ----------------
__device__ __forceinline__ void fma2(unsigned long long& d, unsigned long long a, unsigned long long b) {
    asm("fma.rn.f32x2 %0, %1, %2, %0;" : "+l"(d) : "l"(a), "l"(b));
}
__device__ __forceinline__ unsigned long long pk2(float lo, float hi) {
    unsigned long long r;
    asm("mov.b64 %0, {%1, %2};" : "=l"(r) : "f"(lo), "f"(hi));
    return r;
}
__device__ __forceinline__ float2 upk2(unsigned long long v) {
    float2 f;
    asm("mov.b64 {%0, %1}, %2;" : "=f"(f.x), "=f"(f.y) : "l"(v));
    return f;
}

// ---------------- CSR build ----------------
__global__ void k_init0(int n) {
    int i = blockIdx.x * blockDim.x + threadIdx.x;
    if (i < n) d_cnt[i] = 0;
    if (i < 2) d_csum[i] = 0.0f;
}

// 4 edges per thread via int4
__global__ void k_hist(const int* __restrict__ dst, int E) {
    int q = blockIdx.x * blockDim.x + threadIdx.x;
    int e = q * 4;
    if (e + 4 <= E) {
        int4 d4 = *(const int4*)&dst[e];
        atomicAdd(&d_cnt[d4.x], 1);
        atomicAdd(&d_cnt[d4.y], 1);
        atomicAdd(&d_cnt[d4.z], 1);
        atomicAdd(&d_cnt[d4.w], 1);
    } else {
        for (int k = e; k < E; k++) atomicAdd(&d_cnt[dst[k]], 1);
    }
}

__global__ void k_scanA(int n) {
    __shared__ int sh[256];
    int t = threadIdx.x, b = blockIdx.x;
    int base = b * 1024 + t * 4;
    int s = 0;
    #pragma unroll
    for (int j = 0; j < 4; j++) { int i = base + j; if (i < n) s += d_cnt[i]; }
    sh[t] = s; __syncthreads();
    #pragma unroll
    for (int o = 128; o; o >>= 1) {
        if (t < o) sh[t] += sh[t + o];
        __syncthreads();
    }
    if (t == 0) d_blk[b] = sh[0];
}

__global__ void k_scanB(int nb) {
    __shared__ int sh[256];
    int t = threadIdx.x;
    int v = (t < nb) ? d_blk[t] : 0;
    sh[t] = v; __syncthreads();
    for (int o = 1; o < 256; o <<= 1) {
        int tv = (t >= o) ? sh[t - o] : 0;
        __syncthreads();
        sh[t] += tv;
        __syncthreads();
    }
    if (t < nb) d_blk[t] = sh[t] - v;   // exclusive
}

__global__ void k_scanC(int n) {
    __shared__ int sh[256];
    int t = threadIdx.x, b = blockIdx.x;
    int base = b * 1024 + t * 4;
    int v[4];
    #pragma unroll
    for (int j = 0; j < 4; j++) { int i = base + j; v[j] = (i < n) ? d_cnt[i] : 0; }
    int tsum = v[0] + v[1] + v[2] + v[3];
    sh[t] = tsum; __syncthreads();
    for (int o = 1; o < 256; o <<= 1) {
        int tv = (t >= o) ? sh[t - o] : 0;
        __syncthreads();
        sh[t] += tv;
        __syncthreads();
    }
    int run = sh[t] - tsum + d_blk[b];
    #pragma unroll
    for (int j = 0; j < 4; j++) {
        int i = base + j;
        if (i < n) { d_roff[i] = run; d_cursor[i] = run; }
        run += v[j];
        if (i == n - 1) d_roff[n] = run;
    }
}

__global__ void k_scatter(const int* __restrict__ src, const int* __restrict__ dst, int E) {
    int q = blockIdx.x * blockDim.x + threadIdx.x;
    int e = q * 2;
    if (e + 2 <= E) {
        int2 s2 = *(const int2*)&src[e];
        int2 d2 = *(const int2*)&dst[e];
        int p0 = atomicAdd(&d_cursor[d2.x], 1);
        d_ssrc[p0] = s2.x;
        int p1 = atomicAdd(&d_cursor[d2.y], 1);
        d_ssrc[p1] = s2.y;
    } else {
        for (int k = e; k < E; k++) {
            int p = atomicAdd(&d_cursor[dst[k]], 1);
            d_ssrc[p] = src[k];
        }
    }
}

// ---------------- dense math ----------------

// h1p = (x @ W1) * dinv[row] -> fp16.  Depends only on d_cnt (histogram).
__global__ void k_gemm1(const float* __restrict__ x, const float* __restrict__ W, int n) {
    __shared__ float xs[64][33];
    __shared__ float ws[32][64];
    int t  = threadIdx.x;
    int ty = t >> 4, tx = t & 15;
    int m0 = blockIdx.x * 64;
    unsigned long long acc[4][2] = {};

    for (int kc = 0; kc < 128; kc += 32) {
        #pragma unroll
        for (int q = 0; q < 2; q++) {                 // x tile: 64x32
            int id = t + q * 256;
            int r = id >> 3;
            int c = (id & 7) * 4;
            int node = m0 + r;
            float4 v = make_float4(0.f, 0.f, 0.f, 0.f);
            if (node < n) v = *(const float4*)&x[node * 128 + kc + c];
            xs[r][c + 0] = v.x; xs[r][c + 1] = v.y;
            xs[r][c + 2] = v.z; xs[r][c + 3] = v.w;
        }
        #pragma unroll
        for (int q = 0; q < 2; q++) {                 // W tile: 32x64
            int id = t + q * 256;
            int r = id >> 4;
            int c = (id & 15) * 4;
            *(float4*)&ws[r][c] = *(const float4*)&W[(kc + r) * 64 + c];
        }
        __syncthreads();
        #pragma unroll
        for (int k = 0; k < 32; k++) {
            float4 b = *(float4*)&ws[k][tx * 4];
            unsigned long long b01 = pk2(b.x, b.y);
            unsigned long long b23 = pk2(b.z, b.w);
            #pragma unroll
            for (int i2 = 0; i2 < 4; i2++) {
                float a = xs[ty * 4 + i2][k];
                unsigned long long aa = pk2(a, a);
                fma2(acc[i2][0], aa, b01);
                fma2(acc[i2][1], aa, b23);
            }
        }
        __syncthreads();
    }
    #pragma unroll
    for (int i2 = 0; i2 < 4; i2++) {
        int node = m0 + ty * 4 + i2;
        if (node < n) {
            float s = rsqrtf((float)d_cnt[node] + 1.0f);   // dinv prescale
            float2 p0 = upk2(acc[i2][0]);
            float2 p1 = upk2(acc[i2][1]);
            __half2* op = (__half2*)&d_h1h[node * 64 + tx * 4];
            op[0] = __floats2half2_rn(p0.x * s, p0.y * s);
            op[1] = __floats2half2_rn(p1.x * s, p1.y * s);
        }
    }
}

// fold W2 @ Wl1 @ Wl2 -> d_W2f[64][2]; folded bias -> d_bc
__global__ void k_fold(const float* __restrict__ W2, const float* __restrict__ Wl1,
                       const float* __restrict__ Wl2, const float* __restrict__ b2,
                       const float* __restrict__ bl1, const float* __restrict__ bl2) {
    __shared__ float A[64][2];
    int i = threadIdx.x;            // 64 threads
    float a0 = 0.f, a1 = 0.f;
    for (int m = 0; m < 32; m++) {
        float w = Wl1[i * 32 + m];
        a0 += w * Wl2[m * 2 + 0];
        a1 += w * Wl2[m * 2 + 1];
    }
    A[i][0] = a0; A[i][1] = a1;
    __syncthreads();
    float f0 = 0.f, f1 = 0.f;
    for (int j = 0; j < 64; j++) {
        float w = W2[i * 64 + j];
        f0 += w * A[j][0];
        f1 += w * A[j][1];
    }
    d_W2f[i * 2 + 0] = f0;
    d_W2f[i * 2 + 1] = f1;
    if (i < 2) {
        float b = bl2[i];
        for (int j = 0; j < 64; j++) b += b2[j] * A[j][i];
        for (int m = 0; m < 32; m++) b += bl1[m] * Wl2[m * 2 + i];
        d_bc[i] = b;
    }
}

// ---------------- fused pull-aggregation #1 ----------------
// warp per node: acc64 in regs <- sum of prescaled h1p[src] rows;
// then g = dinv*(acc+self)+b1, relu, project to 2 via W2f, *dinv -> d_z.
__global__ void k_agg1z(const float* __restrict__ b1, int n) {
    __shared__ float wf[128];
    if (threadIdx.x < 128) wf[threadIdx.x] = d_W2f[threadIdx.x];
    __syncthreads();

    int w = (blockIdx.x * blockDim.x + threadIdx.x) >> 5;
    if (w >= n) return;
    int lane = threadIdx.x & 31;
    int c = lane * 2;

    int start = d_roff[w];
    int cnt   = d_roff[w + 1] - start;

    const __half2* hp = (const __half2*)d_h1h;
    float ax = 0.f, ay = 0.f;
    const int* sp = &d_ssrc[start];
    int j = 0;
    for (; j + 8 <= cnt; j += 8) {
        int s0 = __ldg(&sp[j + 0]);
        int s1 = __ldg(&sp[j + 1]);
        int s2 = __ldg(&sp[j + 2]);
        int s3 = __ldg(&sp[j + 3]);
        int s4 = __ldg(&sp[j + 4]);
        int s5 = __ldg(&sp[j + 5]);
        int s6 = __ldg(&sp[j + 6]);
        int s7 = __ldg(&sp[j + 7]);
        float2 a0 = __half22float2(hp[s0 * 32 + lane]);
        float2 a1 = __half22float2(hp[s1 * 32 + lane]);
        float2 a2 = __half22float2(hp[s2 * 32 + lane]);
        float2 a3 = __half22float2(hp[s3 * 32 + lane]);
        float2 a4 = __half22float2(hp[s4 * 32 + lane]);
        float2 a5 = __half22float2(hp[s5 * 32 + lane]);
        float2 a6 = __half22float2(hp[s6 * 32 + lane]);
        float2 a7 = __half22float2(hp[s7 * 32 + lane]);
        ax += ((a0.x + a1.x) + (a2.x + a3.x)) + ((a4.x + a5.x) + (a6.x + a7.x));
        ay += ((a0.y + a1.y) + (a2.y + a3.y)) + ((a4.y + a5.y) + (a6.y + a7.y));
    }
    for (; j < cnt; j++) {
        int s0 = __ldg(&sp[j]);
        float2 a0 = __half22float2(hp[s0 * 32 + lane]);
        ax += a0.x; ay += a0.y;
    }

    float s = rsqrtf((float)cnt + 1.0f);
    float2 self = __half22float2(hp[w * 32 + lane]);
    float2 bv   = *(const float2*)&b1[c];
    float gx = fmaxf(s * (ax + self.x) + bv.x, 0.f);
    float gy = fmaxf(s * (ay + self.y) + bv.y, 0.f);

    float z0 = gx * wf[2 * c + 0] + gy * wf[2 * c + 2];
    float z1 = gx * wf[2 * c + 1] + gy * wf[2 * c + 3];
    #pragma unroll
    for (int o = 16; o; o >>= 1) {
        z0 += __shfl_xor_sync(0xffffffffu, z0, o);
        z1 += __shfl_xor_sync(0xffffffffu, z1, o);
    }
    if (lane == 0)
        ((float2*)d_z)[w] = make_float2(z0 * s, z1 * s);
}

// ---------------- fused pull-aggregation #2 + logits + exp-sum ----------------
__global__ void k_agg2l(int n) {
    __shared__ float red[16];
    int w = (blockIdx.x * blockDim.x + threadIdx.x) >> 5;
    int lane = threadIdx.x & 31;
    int wid = threadIdx.x >> 5;

    float e0 = 0.f, e1 = 0.f;
    if (w < n) {
        int start = d_roff[w];
        int end   = d_roff[w + 1];
        float z0 = 0.f, z1 = 0.f;
        for (int j = start + lane; j < end; j += 32) {
            int si = __ldg(&d_ssrc[j]);
            float2 zz = ((const float2*)d_z)[si];
            z0 += zz.x; z1 += zz.y;
        }
        #pragma unroll
        for (int o = 16; o; o >>= 1) {
            z0 += __shfl_xor_sync(0xffffffffu, z0, o);
            z1 += __shfl_xor_sync(0xffffffffu, z1, o);
        }
        if (lane == 0) {
            float s = rsqrtf((float)(end - start) + 1.0f);
            float2 self = ((const float2*)d_z)[w];
            float l0 = s * (z0 + self.x) + d_bc[0];
            float l1 = s * (z1 + self.y) + d_bc[1];
            ((float2*)d_logits)[w] = make_float2(l0, l1);
            e0 = expf(l0);
            e1 = expf(l1);
        }
    }
    #pragma unroll
    for (int o = 16; o; o >>= 1) {
        e0 += __shfl_xor_sync(0xffffffffu, e0, o);
        e1 += __shfl_xor_sync(0xffffffffu, e1, o);
    }
    if (lane == 0) { red[2 * wid] = e0; red[2 * wid + 1] = e1; }
    __syncthreads();
    if (threadIdx.x == 0) {
        float s0 = 0.f, s1 = 0.f;
        for (int q = 0; q < 8; q++) { s0 += red[2 * q]; s1 += red[2 * q + 1]; }
        atomicAdd(&d_csum[0], s0);
        atomicAdd(&d_csum[1], s1);
    }
}

__global__ void k_out(float* __restrict__ out, int n) {
    int i = blockIdx.x * blockDim.x + threadIdx.x;
    if (i >= n) return;
    float r0 = 1.0f / d_csum[0], r1 = 1.0f / d_csum[1];
    float2 l = ((const float2*)d_logits)[i];
    out[2 * i + 0] = expf(l.x) * r0;
    out[2 * i + 1] = expf(l.y) * r1;
}

// ---------------- launch ----------------
extern "C" void kernel_launch(void* const* d_in, const int* in_sizes, int n_in,
                              void* d_out, int out_size) {
    const float* x   = (const float*)d_in[0];
    const int*   ei  = (const int*)d_in[1];     // int32 (JAX x64 disabled)
    const float* W1  = (const float*)d_in[2];
    const float* b1  = (const float*)d_in[3];
    const float* W2  = (const float*)d_in[4];
    const float* b2  = (const float*)d_in[5];
    const float* Wl1 = (const float*)d_in[6];
    const float* bl1 = (const float*)d_in[7];
    const float* Wl2 = (const float*)d_in[8];
    const float* bl2 = (const float*)d_in[9];
    float* out = (float*)d_out;

    int n = in_sizes[0] / 128;
    int E = in_sizes[1] / 2;
    const int* src = ei;
    const int* dst = ei + E;
    int nb = (n + 1023) / 1024;

    static cudaStream_t s1 = 0;
    static cudaEvent_t evHist = 0, evGemm = 0;
    if (!s1) {
        cudaStreamCreateWithFlags(&s1, cudaStreamNonBlocking);
        cudaEventCreateWithFlags(&evHist, cudaEventDisableTiming);
        cudaEventCreateWithFlags(&evGemm, cudaEventDisableTiming);
    }

    // stream 0: init + hist
    k_init0  <<<(n + 255) / 256, 256>>>(n);
    k_hist   <<<(E / 4 + 255) / 256, 256>>>(dst, E);
    cudaEventRecord(evHist, 0);

    // s1: gemm (needs d_cnt for prescale) + fold — overlaps scans + scatter
    cudaStreamWaitEvent(s1, evHist, 0);
    k_gemm1 <<<(n + 63) / 64, 256, 0, s1>>>(x, W1, n);
    k_fold  <<<1, 64, 0, s1>>>(W2, Wl1, Wl2, b2, bl1, bl2);
    cudaEventRecord(evGemm, s1);

    // stream 0: CSR offsets + scatter
    k_scanA  <<<nb, 256>>>(n);
    k_scanB  <<<1, 256>>>(nb);
    k_scanC  <<<nb, 256>>>(n);
    k_scatter<<<(E / 2 + 255) / 256, 256>>>(src, dst, E);

    // join
    cudaStreamWaitEvent(0, evGemm, 0);
    k_agg1z  <<<(n * 32 + 255) / 256, 256>>>(b1, n);
    k_agg2l  <<<(n * 32 + 255) / 256, 256>>>(n);
    k_out    <<<(n + 255) / 256, 256>>>(out, n);
}

// round 9
// speedup vs baseline: 1.2596x; 1.0198x over previous
#include <cuda_runtime.h>
#include <cuda_fp16.h>

// ---------------- static scratch (no allocation allowed) ----------------
#define N_MAX 100032
#define E_MAX 3400000

__device__ __align__(256) __half d_h1h[100000 * 64]; // h1 * dinv (prescaled), fp16
__device__ __align__(256) float d_z[100000 * 2];     // (relu(g1)@W2f) * dinv
__device__ __align__(256) float d_logits[100000 * 2];
__device__ __align__(256) int   d_cnt[N_MAX];        // in-degree histogram (excl self)
__device__ __align__(256) int   d_roff[N_MAX + 1];   // CSR row offsets
__device__ __align__(256) int   d_cursor[N_MAX];     // scatter cursors
__device__ __align__(256) int   d_ssrc[E_MAX];       // src sorted by dst
__device__ __align__(256) int   d_blk[256];          // scan block sums
__device__ float d_W2f[64 * 2];                      // W2 @ Wl1 @ Wl2
__device__ float d_bc[2];                            // folded bias
__device__ float d_csum[2];

// ---------------- helpers ----------------
__device__ __forceinline__ void fma2(unsigned long long& d, unsigned long long a, unsigned long long b) {
    asm("fma.rn.f32x2 %0, %1, %2, %0;" : "+l"(d) : "l"(a), "l"(b));
}
__device__ __forceinline__ unsigned long long pk2(float lo, float hi) {
    unsigned long long r;
    asm("mov.b64 %0, {%1, %2};" : "=l"(r) : "f"(lo), "f"(hi));
    return r;
}
__device__ __forceinline__ float2 upk2(unsigned long long v) {
    float2 f;
    asm("mov.b64 {%0, %1}, %2;" : "=f"(f.x), "=f"(f.y) : "l"(v));
    return f;
}

// ---------------- CSR build ----------------

// 4 edges per thread via int4
__global__ void k_hist(const int* __restrict__ dst, int E) {
    int q = blockIdx.x * blockDim.x + threadIdx.x;
    int e = q * 4;
    if (e + 4 <= E) {
        int4 d4 = *(const int4*)&dst[e];
        atomicAdd(&d_cnt[d4.x], 1);
        atomicAdd(&d_cnt[d4.y], 1);
        atomicAdd(&d_cnt[d4.z], 1);
        atomicAdd(&d_cnt[d4.w], 1);
    } else {
        for (int k = e; k < E; k++) atomicAdd(&d_cnt[dst[k]], 1);
    }
}

__global__ void k_scanA(int n) {
    __shared__ int sh[256];
    int t = threadIdx.x, b = blockIdx.x;
    int base = b * 1024 + t * 4;
    int s = 0;
    #pragma unroll
    for (int j = 0; j < 4; j++) { int i = base + j; if (i < n) s += d_cnt[i]; }
    sh[t] = s; __syncthreads();
    #pragma unroll
    for (int o = 128; o; o >>= 1) {
        if (t < o) sh[t] += sh[t + o];
        __syncthreads();
    }
    if (t == 0) d_blk[b] = sh[0];
}

__global__ void k_scanB(int nb) {
    __shared__ int sh[256];
    int t = threadIdx.x;
    int v = (t < nb) ? d_blk[t] : 0;
    sh[t] = v; __syncthreads();
    for (int o = 1; o < 256; o <<= 1) {
        int tv = (t >= o) ? sh[t - o] : 0;
        __syncthreads();
        sh[t] += tv;
        __syncthreads();
    }
    if (t < nb) d_blk[t] = sh[t] - v;   // exclusive
}

__global__ void k_scanC(int n) {
    __shared__ int sh[256];
    int t = threadIdx.x, b = blockIdx.x;
    int base = b * 1024 + t * 4;
    int v[4];
    #pragma unroll
    for (int j = 0; j < 4; j++) { int i = base + j; v[j] = (i < n) ? d_cnt[i] : 0; }
    int tsum = v[0] + v[1] + v[2] + v[3];
    sh[t] = tsum; __syncthreads();
    for (int o = 1; o < 256; o <<= 1) {
        int tv = (t >= o) ? sh[t - o] : 0;
        __syncthreads();
        sh[t] += tv;
        __syncthreads();
    }
    int run = sh[t] - tsum + d_blk[b];
    #pragma unroll
    for (int j = 0; j < 4; j++) {
        int i = base + j;
        if (i < n) { d_roff[i] = run; d_cursor[i] = run; }
        run += v[j];
        if (i == n - 1) d_roff[n] = run;
    }
}

// 4 edges per thread
__global__ void k_scatter(const int* __restrict__ src, const int* __restrict__ dst, int E) {
    int q = blockIdx.x * blockDim.x + threadIdx.x;
    int e = q * 4;
    if (e + 4 <= E) {
        int4 s4 = *(const int4*)&src[e];
        int4 d4 = *(const int4*)&dst[e];
        int p0 = atomicAdd(&d_cursor[d4.x], 1); d_ssrc[p0] = s4.x;
        int p1 = atomicAdd(&d_cursor[d4.y], 1); d_ssrc[p1] = s4.y;
        int p2 = atomicAdd(&d_cursor[d4.z], 1); d_ssrc[p2] = s4.z;
        int p3 = atomicAdd(&d_cursor[d4.w], 1); d_ssrc[p3] = s4.w;
    } else {
        for (int k = e; k < E; k++) {
            int p = atomicAdd(&d_cursor[dst[k]], 1);
            d_ssrc[p] = src[k];
        }
    }
}

// ---------------- dense math ----------------

// h1p = (x @ W1) * dinv[row] -> fp16.  Depends only on d_cnt (histogram).
__global__ void k_gemm1(const float* __restrict__ x, const float* __restrict__ W, int n) {
    __shared__ float xs[64][33];
    __shared__ float ws[32][64];
    int t  = threadIdx.x;
    int ty = t >> 4, tx = t & 15;
    int m0 = blockIdx.x * 64;
    unsigned long long acc[4][2] = {};

    for (int kc = 0; kc < 128; kc += 32) {
        #pragma unroll
        for (int q = 0; q < 2; q++) {                 // x tile: 64x32
            int id = t + q * 256;
            int r = id >> 3;
            int c = (id & 7) * 4;
            int node = m0 + r;
            float4 v = make_float4(0.f, 0.f, 0.f, 0.f);
            if (node < n) v = *(const float4*)&x[node * 128 + kc + c];
            xs[r][c + 0] = v.x; xs[r][c + 1] = v.y;
            xs[r][c + 2] = v.z; xs[r][c + 3] = v.w;
        }
        #pragma unroll
        for (int q = 0; q < 2; q++) {                 // W tile: 32x64
            int id = t + q * 256;
            int r = id >> 4;
            int c = (id & 15) * 4;
            *(float4*)&ws[r][c] = *(const float4*)&W[(kc + r) * 64 + c];
        }
        __syncthreads();
        #pragma unroll
        for (int k = 0; k < 32; k++) {
            float4 b = *(float4*)&ws[k][tx * 4];
            unsigned long long b01 = pk2(b.x, b.y);
            unsigned long long b23 = pk2(b.z, b.w);
            #pragma unroll
            for (int i2 = 0; i2 < 4; i2++) {
                float a = xs[ty * 4 + i2][k];
                unsigned long long aa = pk2(a, a);
                fma2(acc[i2][0], aa, b01);
                fma2(acc[i2][1], aa, b23);
            }
        }
        __syncthreads();
    }
    #pragma unroll
    for (int i2 = 0; i2 < 4; i2++) {
        int node = m0 + ty * 4 + i2;
        if (node < n) {
            float s = rsqrtf((float)d_cnt[node] + 1.0f);   // dinv prescale
            float2 p0 = upk2(acc[i2][0]);
            float2 p1 = upk2(acc[i2][1]);
            __half2* op = (__half2*)&d_h1h[node * 64 + tx * 4];
            op[0] = __floats2half2_rn(p0.x * s, p0.y * s);
            op[1] = __floats2half2_rn(p1.x * s, p1.y * s);
        }
    }
}

// fold W2 @ Wl1 @ Wl2 -> d_W2f[64][2]; folded bias -> d_bc; reset csum.
// MUST be launched on a properly capture-forked stream so it is in the graph.
__global__ void k_fold(const float* __restrict__ W2, const float* __restrict__ Wl1,
                       const float* __restrict__ Wl2, const float* __restrict__ b2,
                       const float* __restrict__ bl1, const float* __restrict__ bl2) {
    __shared__ float A[64][2];
    int t = threadIdx.x;
    if (t < 128) {                    // stage 1: A = Wl1 @ Wl2 (128 outputs)
        int i = t >> 1, col = t & 1;
        float a = 0.f;
        #pragma unroll
        for (int m = 0; m < 32; m++)
            a += Wl1[i * 32 + m] * Wl2[m * 2 + col];
        A[i][col] = a;
    }
    if (t == 0) { d_csum[0] = 0.f; d_csum[1] = 0.f; }
    __syncthreads();
    if (t < 128) {                    // stage 2: W2f = W2 @ A (128 outputs)
        int i = t >> 1, col = t & 1;
        float f = 0.f;
        #pragma unroll
        for (int j = 0; j < 64; j++)
            f += W2[i * 64 + j] * A[j][col];
        d_W2f[i * 2 + col] = f;
    }
    if (t < 2) {                      // folded bias
        float b = bl2[t];
        #pragma unroll
        for (int j = 0; j < 64; j++) b += b2[j] * A[j][t];
        #pragma unroll
        for (int m = 0; m < 32; m++) b += bl1[m] * Wl2[m * 2 + t];
        d_bc[t] = b;
    }
}

// ---------------- fused pull-aggregation #1 ----------------
// Prologue: re-zero d_cnt for the next graph replay (cnt is dead here).
__global__ void k_agg1z(const float* __restrict__ b1, int n) {
    __shared__ float wf[128];
    int gtid = blockIdx.x * blockDim.x + threadIdx.x;
    if (gtid < n) d_cnt[gtid] = 0;               // reset for next replay
    if (threadIdx.x < 128) wf[threadIdx.x] = d_W2f[threadIdx.x];
    __syncthreads();

    int w = gtid >> 5;
    if (w >= n) return;
    int lane = threadIdx.x & 31;
    int c = lane * 2;

    int start = d_roff[w];
    int cnt   = d_roff[w + 1] - start;

    const __half2* hp = (const __half2*)d_h1h;
    float ax = 0.f, ay = 0.f;
    const int* sp = &d_ssrc[start];
    int j = 0;
    for (; j + 8 <= cnt; j += 8) {
        int s0 = __ldg(&sp[j + 0]);
        int s1 = __ldg(&sp[j + 1]);
        int s2 = __ldg(&sp[j + 2]);
        int s3 = __ldg(&sp[j + 3]);
        int s4 = __ldg(&sp[j + 4]);
        int s5 = __ldg(&sp[j + 5]);
        int s6 = __ldg(&sp[j + 6]);
        int s7 = __ldg(&sp[j + 7]);
        float2 a0 = __half22float2(hp[s0 * 32 + lane]);
        float2 a1 = __half22float2(hp[s1 * 32 + lane]);
        float2 a2 = __half22float2(hp[s2 * 32 + lane]);
        float2 a3 = __half22float2(hp[s3 * 32 + lane]);
        float2 a4 = __half22float2(hp[s4 * 32 + lane]);
        float2 a5 = __half22float2(hp[s5 * 32 + lane]);
        float2 a6 = __half22float2(hp[s6 * 32 + lane]);
        float2 a7 = __half22float2(hp[s7 * 32 + lane]);
        ax += ((a0.x + a1.x) + (a2.x + a3.x)) + ((a4.x + a5.x) + (a6.x + a7.x));
        ay += ((a0.y + a1.y) + (a2.y + a3.y)) + ((a4.y + a5.y) + (a6.y + a7.y));
    }
    for (; j < cnt; j++) {
        int s0 = __ldg(&sp[j]);
        float2 a0 = __half22float2(hp[s0 * 32 + lane]);
        ax += a0.x; ay += a0.y;
    }

    float s = rsqrtf((float)cnt + 1.0f);
    float2 self = __half22float2(hp[w * 32 + lane]);
    float2 bv   = *(const float2*)&b1[c];
    float gx = fmaxf(s * (ax + self.x) + bv.x, 0.f);
    float gy = fmaxf(s * (ay + self.y) + bv.y, 0.f);

    float z0 = gx * wf[2 * c + 0] + gy * wf[2 * c + 2];
    float z1 = gx * wf[2 * c + 1] + gy * wf[2 * c + 3];
    #pragma unroll
    for (int o = 16; o; o >>= 1) {
        z0 += __shfl_xor_sync(0xffffffffu, z0, o);
        z1 += __shfl_xor_sync(0xffffffffu, z1, o);
    }
    if (lane == 0)
        ((float2*)d_z)[w] = make_float2(z0 * s, z1 * s);
}

// ---------------- fused pull-aggregation #2 + logits + exp-sum ----------------
__global__ void k_agg2l(int n) {
    __shared__ float red[16];
    int w = (blockIdx.x * blockDim.x + threadIdx.x) >> 5;
    int lane = threadIdx.x & 31;
    int wid = threadIdx.x >> 5;

    float e0 = 0.f, e1 = 0.f;
    if (w < n) {
        int start = d_roff[w];
        int end   = d_roff[w + 1];
        float z0 = 0.f, z1 = 0.f;
        for (int j = start + lane; j < end; j += 32) {
            int si = __ldg(&d_ssrc[j]);
            float2 zz = ((const float2*)d_z)[si];
            z0 += zz.x; z1 += zz.y;
        }
        #pragma unroll
        for (int o = 16; o; o >>= 1) {
            z0 += __shfl_xor_sync(0xffffffffu, z0, o);
            z1 += __shfl_xor_sync(0xffffffffu, z1, o);
        }
        if (lane == 0) {
            float s = rsqrtf((float)(end - start) + 1.0f);
            float2 self = ((const float2*)d_z)[w];
            float l0 = s * (z0 + self.x) + d_bc[0];
            float l1 = s * (z1 + self.y) + d_bc[1];
            ((float2*)d_logits)[w] = make_float2(l0, l1);
            e0 = expf(l0);
            e1 = expf(l1);
        }
    }
    #pragma unroll
    for (int o = 16; o; o >>= 1) {
        e0 += __shfl_xor_sync(0xffffffffu, e0, o);
        e1 += __shfl_xor_sync(0xffffffffu, e1, o);
    }
    if (lane == 0) { red[2 * wid] = e0; red[2 * wid + 1] = e1; }
    __syncthreads();
    if (threadIdx.x == 0) {
        float s0 = 0.f, s1 = 0.f;
        for (int q = 0; q < 8; q++) { s0 += red[2 * q]; s1 += red[2 * q + 1]; }
        atomicAdd(&d_csum[0], s0);
        atomicAdd(&d_csum[1], s1);
    }
}

__global__ void k_out(float* __restrict__ out, int n) {
    int i = blockIdx.x * blockDim.x + threadIdx.x;
    if (i >= n) return;
    float r0 = 1.0f / d_csum[0], r1 = 1.0f / d_csum[1];
    float2 l = ((const float2*)d_logits)[i];
    out[2 * i + 0] = expf(l.x) * r0;
    out[2 * i + 1] = expf(l.y) * r1;
}

// ---------------- launch ----------------
extern "C" void kernel_launch(void* const* d_in, const int* in_sizes, int n_in,
                              void* d_out, int out_size) {
    const float* x   = (const float*)d_in[0];
    const int*   ei  = (const int*)d_in[1];     // int32 (JAX x64 disabled)
    const float* W1  = (const float*)d_in[2];
    const float* b1  = (const float*)d_in[3];
    const float* W2  = (const float*)d_in[4];
    const float* b2  = (const float*)d_in[5];
    const float* Wl1 = (const float*)d_in[6];
    const float* bl1 = (const float*)d_in[7];
    const float* Wl2 = (const float*)d_in[8];
    const float* bl2 = (const float*)d_in[9];
    float* out = (float*)d_out;

    int n = in_sizes[0] / 128;
    int E = in_sizes[1] / 2;
    const int* src = ei;
    const int* dst = ei + E;
    int nb = (n + 1023) / 1024;

    static cudaStream_t s1 = 0;
    static cudaEvent_t evFork = 0, evHist = 0, evGemm = 0;
    if (!s1) {
        cudaStreamCreateWithFlags(&s1, cudaStreamNonBlocking);
        cudaEventCreateWithFlags(&evFork, cudaEventDisableTiming);
        cudaEventCreateWithFlags(&evHist, cudaEventDisableTiming);
        cudaEventCreateWithFlags(&evGemm, cudaEventDisableTiming);
    }

    // Fork s1 FROM stream 0 so everything on s1 is part of the captured graph.
    cudaEventRecord(evFork, 0);
    cudaStreamWaitEvent(s1, evFork, 0);

    // s1: fold (csum reset + weight folding) — overlaps hist
    k_fold  <<<1, 256, 0, s1>>>(W2, Wl1, Wl2, b2, bl1, bl2);

    // stream 0: hist (d_cnt zeroed by previous replay's agg1z / static init)
    k_hist  <<<(E / 4 + 255) / 256, 256>>>(dst, E);
    cudaEventRecord(evHist, 0);

    // s1: gemm (needs d_cnt for prescale) — overlaps scans + scatter
    cudaStreamWaitEvent(s1, evHist, 0);
    k_gemm1 <<<(n + 63) / 64, 256, 0, s1>>>(x, W1, n);
    cudaEventRecord(evGemm, s1);

    // stream 0: CSR offsets + scatter
    k_scanA  <<<nb, 256>>>(n);
    k_scanB  <<<1, 256>>>(nb);
    k_scanC  <<<nb, 256>>>(n);
    k_scatter<<<(E / 4 + 255) / 256, 256>>>(src, dst, E);

    // join
    cudaStreamWaitEvent(0, evGemm, 0);
    k_agg1z  <<<(n * 32 + 255) / 256, 256>>>(b1, n);
    k_agg2l  <<<(n * 32 + 255) / 256, 256>>>(n);
    k_out    <<<(n + 255) / 256, 256>>>(out, n);
}

// round 10
// speedup vs baseline: 1.3808x; 1.0962x over previous
#include <cuda_runtime.h>
#include <cuda_fp16.h>

// ---------------- static scratch (no allocation allowed) ----------------
#define N_MAX 100032
#define E_MAX 3400000

__device__ __align__(256) __half d_h1h[100000 * 64]; // h1 * dinv (prescaled), fp16
__device__ __align__(256) float d_z[100000 * 2];     // (relu(g1)@W2f) * dinv
__device__ __align__(256) float d_elog[100000 * 2];  // exp(logits)
__device__ __align__(256) int   d_cnt[N_MAX];        // in-degree histogram (excl self)
__device__ __align__(256) int   d_roff[N_MAX + 1];   // CSR row offsets
__device__ __align__(256) int   d_cursor[N_MAX];     // scatter cursors
__device__ __align__(256) int   d_ssrc[E_MAX];       // src sorted by dst
__device__ __align__(256) long long d_pack[128];     // lookback: (flag<<32)|value
__device__ float d_W2f[64 * 2];                      // W2 @ Wl1 @ Wl2
__device__ float d_bc[2];                            // folded bias
__device__ float d_csum[2];
__device__ int   d_done;

// ---------------- helpers ----------------
__device__ __forceinline__ void fma2(unsigned long long& d, unsigned long long a, unsigned long long b) {
    asm("fma.rn.f32x2 %0, %1, %2, %0;" : "+l"(d) : "l"(a), "l"(b));
}
__device__ __forceinline__ unsigned long long pk2(float lo, float hi) {
    unsigned long long r;
    asm("mov.b64 %0, {%1, %2};" : "=l"(r) : "f"(lo), "f"(hi));
    return r;
}
__device__ __forceinline__ float2 upk2(unsigned long long v) {
    float2 f;
    asm("mov.b64 {%0, %1}, %2;" : "=f"(f.x), "=f"(f.y) : "l"(v));
    return f;
}

// ---------------- CSR build ----------------

// 4 edges per thread via int4; also resets the scan-lookback state for this replay.
__global__ void k_hist(const int* __restrict__ dst, int E) {
    int q = blockIdx.x * blockDim.x + threadIdx.x;
    if (q < 128) d_pack[q] = 0;                 // lookback reset (in-stream before scan)
    int e = q * 4;
    if (e + 4 <= E) {
        int4 d4 = *(const int4*)&dst[e];
        atomicAdd(&d_cnt[d4.x], 1);
        atomicAdd(&d_cnt[d4.y], 1);
        atomicAdd(&d_cnt[d4.z], 1);
        atomicAdd(&d_cnt[d4.w], 1);
    } else {
        for (int k = e; k < E; k++) atomicAdd(&d_cnt[dst[k]], 1);
    }
}

// Single-kernel exclusive scan over d_cnt via decoupled lookback.
// 1024 elems/block, 256 threads. <=98 blocks for n<=100352 (single wave, no deadlock).
__global__ void k_scan(int n, int E) {
    __shared__ int sh[256];
    __shared__ int s_ex;
    int t = threadIdx.x, b = blockIdx.x;
    int base = b * 1024 + t * 4;
    int v[4];
    #pragma unroll
    for (int j = 0; j < 4; j++) { int i = base + j; v[j] = (i < n) ? d_cnt[i] : 0; }
    int tsum = v[0] + v[1] + v[2] + v[3];
    sh[t] = tsum; __syncthreads();
    for (int o = 1; o < 256; o <<= 1) {
        int tv = (t >= o) ? sh[t - o] : 0;
        __syncthreads();
        sh[t] += tv;
        __syncthreads();
    }
    int blockAgg = sh[255];

    if (t == 0) {   // publish aggregate (block 0 publishes prefix directly)
        long long pk = ((long long)((b == 0) ? 2 : 1) << 32) | (unsigned)blockAgg;
        *((volatile long long*)&d_pack[b]) = pk;
        if (b == 0) s_ex = 0;
    }
    if (b > 0 && t < 32) {          // warp-parallel lookback
        int ex = 0;
        int look = b - 1;
        while (true) {
            int idx = look - t;
            long long pk = 0;
            if (idx >= 0) {
                do { pk = *((volatile long long*)&d_pack[idx]); } while ((int)(pk >> 32) == 0);
            }
            int flag = (int)(pk >> 32);
            int val  = (int)(unsigned)pk;
            unsigned pm = __ballot_sync(0xffffffffu, flag == 2);
            if (pm) {
                int fp = __ffs(pm) - 1;              // nearest prefix lane
                int contrib = (t <= fp) ? val : 0;
                #pragma unroll
                for (int o = 16; o; o >>= 1) contrib += __shfl_xor_sync(0xffffffffu, contrib, o);
                ex += contrib;
                break;
            } else {
                int contrib = (idx >= 0) ? val : 0;
                #pragma unroll
                for (int o = 16; o; o >>= 1) contrib += __shfl_xor_sync(0xffffffffu, contrib, o);
                ex += contrib;
                look -= 32;
            }
        }
        if (t == 0) {
            s_ex = ex;
            long long pk = ((long long)2 << 32) | (unsigned)(ex + blockAgg);   // inclusive prefix
            *((volatile long long*)&d_pack[b]) = pk;
        }
    }
    __syncthreads();
    int run = s_ex + sh[t] - tsum;
    #pragma unroll
    for (int j = 0; j < 4; j++) {
        int i = base + j;
        if (i < n) { d_roff[i] = run; d_cursor[i] = run; }
        run += v[j];
    }
    if (b == 0 && t == 0) d_roff[n] = E;
}

// 4 edges per thread
__global__ void k_scatter(const int* __restrict__ src, const int* __restrict__ dst, int E) {
    int q = blockIdx.x * blockDim.x + threadIdx.x;
    int e = q * 4;
    if (e + 4 <= E) {
        int4 s4 = *(const int4*)&src[e];
        int4 d4 = *(const int4*)&dst[e];
        int p0 = atomicAdd(&d_cursor[d4.x], 1); d_ssrc[p0] = s4.x;
        int p1 = atomicAdd(&d_cursor[d4.y], 1); d_ssrc[p1] = s4.y;
        int p2 = atomicAdd(&d_cursor[d4.z], 1); d_ssrc[p2] = s4.z;
        int p3 = atomicAdd(&d_cursor[d4.w], 1); d_ssrc[p3] = s4.w;
    } else {
        for (int k = e; k < E; k++) {
            int p = atomicAdd(&d_cursor[dst[k]], 1);
            d_ssrc[p] = src[k];
        }
    }
}

// ---------------- dense math ----------------

// h1p = (x @ W1) * dinv[row] -> fp16.  Depends only on d_cnt (histogram).
__global__ void k_gemm1(const float* __restrict__ x, const float* __restrict__ W, int n) {
    __shared__ float xs[64][33];
    __shared__ float ws[32][64];
    int t  = threadIdx.x;
    int ty = t >> 4, tx = t & 15;
    int m0 = blockIdx.x * 64;
    unsigned long long acc[4][2] = {};

    for (int kc = 0; kc < 128; kc += 32) {
        #pragma unroll
        for (int q = 0; q < 2; q++) {                 // x tile: 64x32
            int id = t + q * 256;
            int r = id >> 3;
            int c = (id & 7) * 4;
            int node = m0 + r;
            float4 v = make_float4(0.f, 0.f, 0.f, 0.f);
            if (node < n) v = *(const float4*)&x[node * 128 + kc + c];
            xs[r][c + 0] = v.x; xs[r][c + 1] = v.y;
            xs[r][c + 2] = v.z; xs[r][c + 3] = v.w;
        }
        #pragma unroll
        for (int q = 0; q < 2; q++) {                 // W tile: 32x64
            int id = t + q * 256;
            int r = id >> 4;
            int c = (id & 15) * 4;
            *(float4*)&ws[r][c] = *(const float4*)&W[(kc + r) * 64 + c];
        }
        __syncthreads();
        #pragma unroll
        for (int k = 0; k < 32; k++) {
            float4 b = *(float4*)&ws[k][tx * 4];
            unsigned long long b01 = pk2(b.x, b.y);
            unsigned long long b23 = pk2(b.z, b.w);
            #pragma unroll
            for (int i2 = 0; i2 < 4; i2++) {
                float a = xs[ty * 4 + i2][k];
                unsigned long long aa = pk2(a, a);
                fma2(acc[i2][0], aa, b01);
                fma2(acc[i2][1], aa, b23);
            }
        }
        __syncthreads();
    }
    #pragma unroll
    for (int i2 = 0; i2 < 4; i2++) {
        int node = m0 + ty * 4 + i2;
        if (node < n) {
            float s = rsqrtf((float)d_cnt[node] + 1.0f);   // dinv prescale
            float2 p0 = upk2(acc[i2][0]);
            float2 p1 = upk2(acc[i2][1]);
            __half2* op = (__half2*)&d_h1h[node * 64 + tx * 4];
            op[0] = __floats2half2_rn(p0.x * s, p0.y * s);
            op[1] = __floats2half2_rn(p1.x * s, p1.y * s);
        }
    }
}

// fold W2 @ Wl1 @ Wl2 -> d_W2f; folded bias -> d_bc; reset csum + done.
__global__ void k_fold(const float* __restrict__ W2, const float* __restrict__ Wl1,
                       const float* __restrict__ Wl2, const float* __restrict__ b2,
                       const float* __restrict__ bl1, const float* __restrict__ bl2) {
    __shared__ float A[64][2];
    int t = threadIdx.x;
    if (t < 128) {                    // stage 1: A = Wl1 @ Wl2
        int i = t >> 1, col = t & 1;
        float a = 0.f;
        #pragma unroll
        for (int m = 0; m < 32; m++)
            a += Wl1[i * 32 + m] * Wl2[m * 2 + col];
        A[i][col] = a;
    }
    if (t == 0) { d_csum[0] = 0.f; d_csum[1] = 0.f; d_done = 0; }
    __syncthreads();
    if (t < 128) {                    // stage 2: W2f = W2 @ A
        int i = t >> 1, col = t & 1;
        float f = 0.f;
        #pragma unroll
        for (int j = 0; j < 64; j++)
            f += W2[i * 64 + j] * A[j][col];
        d_W2f[i * 2 + col] = f;
    }
    if (t < 2) {
        float b = bl2[t];
        #pragma unroll
        for (int j = 0; j < 64; j++) b += b2[j] * A[j][t];
        #pragma unroll
        for (int m = 0; m < 32; m++) b += bl1[m] * Wl2[m * 2 + t];
        d_bc[t] = b;
    }
}

// ---------------- fused pull-aggregation #1 ----------------
__global__ void k_agg1z(const float* __restrict__ b1, int n) {
    __shared__ float wf[128];
    int gtid = blockIdx.x * blockDim.x + threadIdx.x;
    if (gtid < n) d_cnt[gtid] = 0;               // reset for next replay
    if (threadIdx.x < 128) wf[threadIdx.x] = d_W2f[threadIdx.x];
    __syncthreads();

    int w = gtid >> 5;
    if (w >= n) return;
    int lane = threadIdx.x & 31;
    int c = lane * 2;

    int start = d_roff[w];
    int cnt   = d_roff[w + 1] - start;

    const __half2* hp = (const __half2*)d_h1h;
    float ax = 0.f, ay = 0.f;
    const int* sp = &d_ssrc[start];
    int j = 0;
    for (; j + 8 <= cnt; j += 8) {
        int s0 = __ldg(&sp[j + 0]);
        int s1 = __ldg(&sp[j + 1]);
        int s2 = __ldg(&sp[j + 2]);
        int s3 = __ldg(&sp[j + 3]);
        int s4 = __ldg(&sp[j + 4]);
        int s5 = __ldg(&sp[j + 5]);
        int s6 = __ldg(&sp[j + 6]);
        int s7 = __ldg(&sp[j + 7]);
        float2 a0 = __half22float2(hp[s0 * 32 + lane]);
        float2 a1 = __half22float2(hp[s1 * 32 + lane]);
        float2 a2 = __half22float2(hp[s2 * 32 + lane]);
        float2 a3 = __half22float2(hp[s3 * 32 + lane]);
        float2 a4 = __half22float2(hp[s4 * 32 + lane]);
        float2 a5 = __half22float2(hp[s5 * 32 + lane]);
        float2 a6 = __half22float2(hp[s6 * 32 + lane]);
        float2 a7 = __half22float2(hp[s7 * 32 + lane]);
        ax += ((a0.x + a1.x) + (a2.x + a3.x)) + ((a4.x + a5.x) + (a6.x + a7.x));
        ay += ((a0.y + a1.y) + (a2.y + a3.y)) + ((a4.y + a5.y) + (a6.y + a7.y));
    }
    for (; j < cnt; j++) {
        int s0 = __ldg(&sp[j]);
        float2 a0 = __half22float2(hp[s0 * 32 + lane]);
        ax += a0.x; ay += a0.y;
    }

    float s = rsqrtf((float)cnt + 1.0f);
    float2 self = __half22float2(hp[w * 32 + lane]);
    float2 bv   = *(const float2*)&b1[c];
    float gx = fmaxf(s * (ax + self.x) + bv.x, 0.f);
    float gy = fmaxf(s * (ay + self.y) + bv.y, 0.f);

    float z0 = gx * wf[2 * c + 0] + gy * wf[2 * c + 2];
    float z1 = gx * wf[2 * c + 1] + gy * wf[2 * c + 3];
    #pragma unroll
    for (int o = 16; o; o >>= 1) {
        z0 += __shfl_xor_sync(0xffffffffu, z0, o);
        z1 += __shfl_xor_sync(0xffffffffu, z1, o);
    }
    if (lane == 0)
        ((float2*)d_z)[w] = make_float2(z0 * s, z1 * s);
}

// ---------------- persistent agg2 + softmax + output ----------------
// grid = SMs*4 blocks of 256 (single wave guaranteed) -> spin barrier is safe.
__global__ void __launch_bounds__(256)
k_agg2out(float* __restrict__ out, int n, int G) {
    __shared__ float red[16];
    int lane = threadIdx.x & 31;
    int wid  = threadIdx.x >> 5;
    int gw0  = (blockIdx.x * blockDim.x + threadIdx.x) >> 5;
    int tw   = (gridDim.x * blockDim.x) >> 5;

    float bc0 = d_bc[0], bc1 = d_bc[1];
    float e0 = 0.f, e1 = 0.f;
    for (int w = gw0; w < n; w += tw) {
        int start = d_roff[w];
        int end   = d_roff[w + 1];
        float z0 = 0.f, z1 = 0.f;
        for (int j = start + lane; j < end; j += 32) {
            int si = __ldg(&d_ssrc[j]);
            float2 zz = ((const float2*)d_z)[si];
            z0 += zz.x; z1 += zz.y;
        }
        #pragma unroll
        for (int o = 16; o; o >>= 1) {
            z0 += __shfl_xor_sync(0xffffffffu, z0, o);
            z1 += __shfl_xor_sync(0xffffffffu, z1, o);
        }
        if (lane == 0) {
            float s = rsqrtf((float)(end - start) + 1.0f);
            float2 self = ((const float2*)d_z)[w];
            float ex0 = expf(s * (z0 + self.x) + bc0);
            float ex1 = expf(s * (z1 + self.y) + bc1);
            ((float2*)d_elog)[w] = make_float2(ex0, ex1);
            e0 += ex0; e1 += ex1;
        }
    }
    #pragma unroll
    for (int o = 16; o; o >>= 1) {
        e0 += __shfl_xor_sync(0xffffffffu, e0, o);
        e1 += __shfl_xor_sync(0xffffffffu, e1, o);
    }
    if (lane == 0) { red[2 * wid] = e0; red[2 * wid + 1] = e1; }
    __syncthreads();
    if (threadIdx.x == 0) {
        float s0 = 0.f, s1 = 0.f;
        #pragma unroll
        for (int q = 0; q < 8; q++) { s0 += red[2 * q]; s1 += red[2 * q + 1]; }
        atomicAdd(&d_csum[0], s0);
        atomicAdd(&d_csum[1], s1);
        __threadfence();
        atomicAdd(&d_done, 1);
        while (*((volatile int*)&d_done) < G) { }
    }
    __syncthreads();
    __threadfence();
    float r0 = 1.0f / *((volatile float*)&d_csum[0]);
    float r1 = 1.0f / *((volatile float*)&d_csum[1]);
    for (int i = blockIdx.x * blockDim.x + threadIdx.x; i < n; i += gridDim.x * blockDim.x) {
        float2 el = ((const float2*)d_elog)[i];
        out[2 * i + 0] = el.x * r0;
        out[2 * i + 1] = el.y * r1;
    }
}

// ---------------- launch ----------------
extern "C" void kernel_launch(void* const* d_in, const int* in_sizes, int n_in,
                              void* d_out, int out_size) {
    const float* x   = (const float*)d_in[0];
    const int*   ei  = (const int*)d_in[1];     // int32 (JAX x64 disabled)
    const float* W1  = (const float*)d_in[2];
    const float* b1  = (const float*)d_in[3];
    const float* W2  = (const float*)d_in[4];
    const float* b2  = (const float*)d_in[5];
    const float* Wl1 = (const float*)d_in[6];
    const float* bl1 = (const float*)d_in[7];
    const float* Wl2 = (const float*)d_in[8];
    const float* bl2 = (const float*)d_in[9];
    float* out = (float*)d_out;

    int n = in_sizes[0] / 128;
    int E = in_sizes[1] / 2;
    const int* src = ei;
    const int* dst = ei + E;
    int nb = (n + 1023) / 1024;   // scan blocks (<=98 for n<=100352)

    static cudaStream_t s1 = 0;
    static cudaEvent_t evFork = 0, evHist = 0, evGemm = 0;
    static int G = 0;
    if (!s1) {
        cudaStreamCreateWithFlags(&s1, cudaStreamNonBlocking);
        cudaEventCreateWithFlags(&evFork, cudaEventDisableTiming);
        cudaEventCreateWithFlags(&evHist, cudaEventDisableTiming);
        cudaEventCreateWithFlags(&evGemm, cudaEventDisableTiming);
        int dev = 0, sms = 0;
        cudaGetDevice(&dev);
        cudaDeviceGetAttribute(&sms, cudaDevAttrMultiProcessorCount, dev);
        G = sms * 4;               // 256 thr/block -> guaranteed single wave
    }

    // Fork s1 FROM stream 0 so s1 work is captured into the graph.
    cudaEventRecord(evFork, 0);
    cudaStreamWaitEvent(s1, evFork, 0);

    // s1: fold (resets csum/done; weight folding) — overlaps hist
    k_fold  <<<1, 256, 0, s1>>>(W2, Wl1, Wl2, b2, bl1, bl2);

    // stream 0: hist (+ lookback-state reset)
    k_hist  <<<(E / 4 + 255) / 256, 256>>>(dst, E);
    cudaEventRecord(evHist, 0);

    // s1: gemm (needs d_cnt for prescale) — overlaps scan + scatter
    cudaStreamWaitEvent(s1, evHist, 0);
    k_gemm1 <<<(n + 63) / 64, 256, 0, s1>>>(x, W1, n);
    cudaEventRecord(evGemm, s1);

    // stream 0: single-kernel scan + scatter
    k_scan   <<<nb, 256>>>(n, E);
    k_scatter<<<(E / 4 + 255) / 256, 256>>>(src, dst, E);

    // join
    cudaStreamWaitEvent(0, evGemm, 0);
    k_agg1z  <<<(n * 32 + 255) / 256, 256>>>(b1, n);
    k_agg2out<<<G, 256>>>(out, n, G);
}